// round 1
// baseline (speedup 1.0000x reference)
#include <cuda_runtime.h>
#include <cuda_bf16.h>
#include <cstdint>

// ----------------------------------------------------------------------------
// GCN: h1 = relu(Agg(x@W1) + b1); h2 = relu(Agg(h1@W2) + b2);
//      g = segment_max(h2, batch); out = g@Wfc + bfc
// Agg(m)[c] = sum_{e: col[e]=c} m[row[e]] * dis[row]*dis[col]  (+ self loop dis[c]^2 * m[c])
// ----------------------------------------------------------------------------

#define N_NODES 50000
#define N_EDGES 800000
#define N_GRAPHS 128
#define IN_DIM 256
#define H1 128
#define H2 64
#define OUT_DIM 10

// Scratch (device globals: allocation-free rule)
__device__ float g_dis[N_NODES];                 // deg -> 1/sqrt(deg) in place
__device__ float g_norm[N_EDGES];
__device__ float g_h1[(size_t)N_NODES * H1];
__device__ float g_agg1[(size_t)N_NODES * H1];
__device__ float g_h2[(size_t)N_NODES * H2];
__device__ float g_agg2[(size_t)N_NODES * H2];
__device__ float g_pool[N_GRAPHS * H2];

// ---------------------------------------------------------------- utilities
__device__ __forceinline__ void red_add_v4(float* addr, float4 v) {
    asm volatile("red.global.add.v4.f32 [%0], {%1, %2, %3, %4};"
                 :: "l"(addr), "f"(v.x), "f"(v.y), "f"(v.z), "f"(v.w)
                 : "memory");
}

// ---------------------------------------------------------------- degree/norm
__global__ void k_init_deg(float* dis) {
    int i = blockIdx.x * blockDim.x + threadIdx.x;
    if (i < N_NODES) dis[i] = 1.0f;   // self loop contributes 1 to deg
}

__global__ void k_deg_edges(const int* __restrict__ col, float* dis) {
    int e = blockIdx.x * blockDim.x + threadIdx.x;
    if (e < N_EDGES) atomicAdd(&dis[col[e]], 1.0f);
}

__global__ void k_dis(float* dis) {
    int i = blockIdx.x * blockDim.x + threadIdx.x;
    if (i < N_NODES) dis[i] = rsqrtf(dis[i]);   // deg >= 1 always
}

__global__ void k_norm(const int* __restrict__ row, const int* __restrict__ col,
                       const float* __restrict__ dis, float* __restrict__ nrm) {
    int e = blockIdx.x * blockDim.x + threadIdx.x;
    if (e < N_EDGES) nrm[e] = dis[row[e]] * dis[col[e]];
}

// ---------------------------------------------------------------- GEMM (tiled fp32)
// C[M,N] = op(A)[M,K] @ B[K,N].  N == BN (single block column).
// FUSE: A element = relu(A[m][k] + bias[k])
template<int BM, int BN, int BK, int TM, int TN, bool FUSE>
__global__ void __launch_bounds__(256)
k_gemm(const float* __restrict__ A, const float* __restrict__ B,
       float* __restrict__ C, const float* __restrict__ bias, int M, int K)
{
    __shared__ float As[BK][BM];
    __shared__ float Bs[BK][BN];
    const int tid = threadIdx.x;
    const int tx = tid % (BN / TN);
    const int ty = tid / (BN / TN);
    const int m0 = blockIdx.x * BM;

    float acc[TM][TN];
#pragma unroll
    for (int i = 0; i < TM; i++)
#pragma unroll
        for (int j = 0; j < TN; j++) acc[i][j] = 0.f;

    for (int k0 = 0; k0 < K; k0 += BK) {
        // --- A tile (transposed into As[k][m]) ---
        constexpr int A4 = BM * BK / 4;
#pragma unroll
        for (int i = tid; i < A4; i += 256) {
            int r  = i / (BK / 4);
            int c4 = i % (BK / 4);
            float4 v = make_float4(0.f, 0.f, 0.f, 0.f);
            if (m0 + r < M) {
                v = *(const float4*)(A + (size_t)(m0 + r) * K + k0 + c4 * 4);
                if (FUSE) {
                    float4 bb = *(const float4*)(bias + k0 + c4 * 4);
                    v.x = fmaxf(v.x + bb.x, 0.f);
                    v.y = fmaxf(v.y + bb.y, 0.f);
                    v.z = fmaxf(v.z + bb.z, 0.f);
                    v.w = fmaxf(v.w + bb.w, 0.f);
                }
            }
            As[c4 * 4 + 0][r] = v.x;
            As[c4 * 4 + 1][r] = v.y;
            As[c4 * 4 + 2][r] = v.z;
            As[c4 * 4 + 3][r] = v.w;
        }
        // --- B tile ---
        constexpr int B4 = BK * BN / 4;
#pragma unroll
        for (int i = tid; i < B4; i += 256) {
            int kk = i / (BN / 4);
            int c4 = i % (BN / 4);
            *(float4*)&Bs[kk][c4 * 4] =
                *(const float4*)(B + (size_t)(k0 + kk) * BN + c4 * 4);
        }
        __syncthreads();

#pragma unroll
        for (int k = 0; k < BK; k++) {
            float a[TM], b[TN];
#pragma unroll
            for (int i = 0; i < TM; i += 4)
                *(float4*)&a[i] = *(const float4*)&As[k][ty * TM + i];
#pragma unroll
            for (int j = 0; j < TN; j += 4)
                *(float4*)&b[j] = *(const float4*)&Bs[k][tx * TN + j];
#pragma unroll
            for (int i = 0; i < TM; i++)
#pragma unroll
                for (int j = 0; j < TN; j++)
                    acc[i][j] = fmaf(a[i], b[j], acc[i][j]);
        }
        __syncthreads();
    }

#pragma unroll
    for (int i = 0; i < TM; i++) {
        int m = m0 + ty * TM + i;
        if (m < M) {
#pragma unroll
            for (int j = 0; j < TN; j += 4) {
                float4 v = make_float4(acc[i][j], acc[i][j + 1], acc[i][j + 2], acc[i][j + 3]);
                *(float4*)(C + (size_t)m * BN + tx * TN + j) = v;
            }
        }
    }
}

// ---------------------------------------------------------------- self-loop init
// agg[i][:] = h[i][:] * dis[i]^2     (F4 = F/4 float4s per node)
template<int F4>
__global__ void k_self_init(const float* __restrict__ h, const float* __restrict__ dis,
                            float* __restrict__ agg)
{
    int idx = blockIdx.x * blockDim.x + threadIdx.x;
    if (idx < N_NODES * F4) {
        int node = idx / F4;
        float s = dis[node];
        s *= s;
        float4 v = ((const float4*)h)[idx];
        v.x *= s; v.y *= s; v.z *= s; v.w *= s;
        ((float4*)agg)[idx] = v;
    }
}

// ---------------------------------------------------------------- edge scatter
// F=128: one warp per edge, each lane one float4.
__global__ void k_scatter128(const int* __restrict__ row, const int* __restrict__ col,
                             const float* __restrict__ nrm,
                             const float* __restrict__ h, float* __restrict__ agg)
{
    int gtid = blockIdx.x * blockDim.x + threadIdx.x;
    int e = gtid >> 5;
    int lane = gtid & 31;
    if (e >= N_EDGES) return;
    int r = row[e], c = col[e];
    float n = nrm[e];
    float4 v = *(const float4*)(h + (size_t)r * 128 + lane * 4);
    v.x *= n; v.y *= n; v.z *= n; v.w *= n;
    red_add_v4((float*)(agg + (size_t)c * 128 + lane * 4), v);
}

// F=64: one warp handles two edges (16 lanes each, one float4 per lane).
__global__ void k_scatter64(const int* __restrict__ row, const int* __restrict__ col,
                            const float* __restrict__ nrm,
                            const float* __restrict__ h, float* __restrict__ agg)
{
    int gtid = blockIdx.x * blockDim.x + threadIdx.x;
    int warp = gtid >> 5;
    int lane = gtid & 31;
    int e = warp * 2 + (lane >> 4);
    int sl = lane & 15;
    if (e >= N_EDGES) return;
    int r = row[e], c = col[e];
    float n = nrm[e];
    float4 v = *(const float4*)(h + (size_t)r * 64 + sl * 4);
    v.x *= n; v.y *= n; v.z *= n; v.w *= n;
    red_add_v4((float*)(agg + (size_t)c * 64 + sl * 4), v);
}

// ---------------------------------------------------------------- max pool
__global__ void k_zero_pool(float* pool) {
    int i = blockIdx.x * blockDim.x + threadIdx.x;
    if (i < N_GRAPHS * H2) pool[i] = 0.f;
}

// Two-stage segment max. batch is sorted, values are relu'd (>=0) so
// uint atomicMax on the float bit pattern is order-preserving and init=0 is safe.
#define POOL_CHUNK 512
__global__ void k_pool(const float* __restrict__ agg2, const float* __restrict__ b2,
                       const int* __restrict__ batch, float* __restrict__ pool)
{
    int f = threadIdx.x;                 // 64 threads = 64 features
    int start = blockIdx.x * POOL_CHUNK;
    int end = start + POOL_CHUNK;
    if (end > N_NODES) end = N_NODES;
    float bb = b2[f];
    int gcur = -1;
    float m = 0.f;
    for (int i = start; i < end; i++) {
        int g = batch[i];
        if (g != gcur) {
            if (gcur >= 0)
                atomicMax((unsigned int*)&pool[gcur * H2 + f], __float_as_uint(m));
            gcur = g;
            m = 0.f;
        }
        float v = agg2[(size_t)i * H2 + f] + bb;
        v = v > 0.f ? v : 0.f;
        m = fmaxf(m, v);
    }
    if (gcur >= 0)
        atomicMax((unsigned int*)&pool[gcur * H2 + f], __float_as_uint(m));
}

// ---------------------------------------------------------------- final FC
__global__ void k_fc(const float* __restrict__ pool, const float* __restrict__ Wfc,
                     const float* __restrict__ bfc, float* __restrict__ out)
{
    __shared__ float w[H2 * OUT_DIM];
    __shared__ float bb[OUT_DIM];
    int tid = threadIdx.x;
    for (int i = tid; i < H2 * OUT_DIM; i += blockDim.x) w[i] = Wfc[i];
    if (tid < OUT_DIM) bb[tid] = bfc[tid];
    __syncthreads();
    if (tid < N_GRAPHS) {
        float acc[OUT_DIM];
#pragma unroll
        for (int j = 0; j < OUT_DIM; j++) acc[j] = bb[j];
        for (int k = 0; k < H2; k++) {
            float g = pool[tid * H2 + k];
#pragma unroll
            for (int j = 0; j < OUT_DIM; j++) acc[j] = fmaf(g, w[k * OUT_DIM + j], acc[j]);
        }
#pragma unroll
        for (int j = 0; j < OUT_DIM; j++) out[tid * OUT_DIM + j] = acc[j];
    }
}

// ---------------------------------------------------------------- launch
extern "C" void kernel_launch(void* const* d_in, const int* in_sizes, int n_in,
                              void* d_out, int out_size)
{
    const float* x    = (const float*)d_in[0];
    const int*   ei   = (const int*)d_in[1];
    const int*   batch= (const int*)d_in[2];
    const float* W1   = (const float*)d_in[3];
    const float* b1   = (const float*)d_in[4];
    const float* W2   = (const float*)d_in[5];
    const float* b2   = (const float*)d_in[6];
    const float* Wfc  = (const float*)d_in[7];
    const float* bfc  = (const float*)d_in[8];
    float* out = (float*)d_out;

    const int* row = ei;
    const int* col = ei + N_EDGES;

    float *dis, *nrm, *h1, *agg1, *h2, *agg2, *pool;
    cudaGetSymbolAddress((void**)&dis,  g_dis);
    cudaGetSymbolAddress((void**)&nrm,  g_norm);
    cudaGetSymbolAddress((void**)&h1,   g_h1);
    cudaGetSymbolAddress((void**)&agg1, g_agg1);
    cudaGetSymbolAddress((void**)&h2,   g_h2);
    cudaGetSymbolAddress((void**)&agg2, g_agg2);
    cudaGetSymbolAddress((void**)&pool, g_pool);

    // degrees + normalization
    k_init_deg<<<(N_NODES + 255) / 256, 256>>>(dis);
    k_deg_edges<<<(N_EDGES + 255) / 256, 256>>>(col, dis);
    k_dis<<<(N_NODES + 255) / 256, 256>>>(dis);
    k_norm<<<(N_EDGES + 255) / 256, 256>>>(row, col, dis, nrm);

    // layer 1: h1 = x @ W1 ; agg1 = self + scatter
    k_gemm<128, 128, 16, 8, 8, false><<<(N_NODES + 127) / 128, 256>>>(
        x, W1, h1, nullptr, N_NODES, IN_DIM);
    k_self_init<H1 / 4><<<(N_NODES * (H1 / 4) + 255) / 256, 256>>>(h1, dis, agg1);
    k_scatter128<<<(N_EDGES * 32 + 255) / 256, 256>>>(row, col, nrm, h1, agg1);

    // layer 2: h2 = relu(agg1 + b1) @ W2 ; agg2 = self + scatter
    k_gemm<128, 64, 16, 8, 4, true><<<(N_NODES + 127) / 128, 256>>>(
        agg1, W2, h2, b1, N_NODES, H1);
    k_self_init<H2 / 4><<<(N_NODES * (H2 / 4) + 255) / 256, 256>>>(h2, dis, agg2);
    k_scatter64<<<(N_EDGES * 16 + 255) / 256, 256>>>(row, col, nrm, h2, agg2);

    // pool + fc
    k_zero_pool<<<(N_GRAPHS * H2 + 255) / 256, 256>>>(pool);
    k_pool<<<(N_NODES + POOL_CHUNK - 1) / POOL_CHUNK, H2>>>(agg2, b2, batch, pool);
    k_fc<<<1, 128>>>(pool, Wfc, bfc, out);
}

// round 2
// speedup vs baseline: 1.0646x; 1.0646x over previous
#include <cuda_runtime.h>
#include <cuda_bf16.h>
#include <cstdint>

// ----------------------------------------------------------------------------
// GCN: h1 = relu(Agg(x@W1) + b1); h2 = relu(Agg(h1@W2) + b2);
//      g = segment_max(h2, batch); out = g@Wfc + bfc
// Agg via CSR gather (atomic-free); GEMMs via tf32 mma.sync tensor cores.
// ----------------------------------------------------------------------------

#define N_NODES 50000
#define N_EDGES 800000
#define N_GRAPHS 128
#define IN_DIM 256
#define H1 128
#define H2 64
#define OUT_DIM 10

// Scratch (device globals: allocation-free rule)
__device__ int   g_deg[N_NODES];
__device__ int   g_off[N_NODES + 1];
__device__ int   g_cursor[N_NODES];
__device__ float g_dis[N_NODES];
__device__ int   g_crow[N_EDGES];
__device__ float g_cnrm[N_EDGES];
__device__ float g_h1[(size_t)N_NODES * H1];
__device__ float g_agg1[(size_t)N_NODES * H1];
__device__ float g_h2[(size_t)N_NODES * H2];
__device__ float g_agg2[(size_t)N_NODES * H2];
__device__ float g_pool[N_GRAPHS * H2];

// ---------------------------------------------------------------- CSR build
__global__ void k_zero_deg(int* deg) {
    int i = blockIdx.x * blockDim.x + threadIdx.x;
    if (i < N_NODES) deg[i] = 0;
}

__global__ void k_count(const int* __restrict__ col, int* deg) {
    int e = blockIdx.x * blockDim.x + threadIdx.x;
    if (e < N_EDGES) atomicAdd(&deg[col[e]], 1);
}

// Single block of 1024 threads: exclusive prefix sum over 50k degrees,
// also computes dis[i] = 1/sqrt(deg+1) (self loop folded into degree).
__global__ void __launch_bounds__(1024)
k_scan(const int* __restrict__ deg, int* __restrict__ off,
       int* __restrict__ cursor, float* __restrict__ dis)
{
    __shared__ int sums[1024];
    const int t = threadIdx.x;
    const int CHUNK = (N_NODES + 1023) / 1024;    // 49
    int lo = t * CHUNK; if (lo > N_NODES) lo = N_NODES;
    int hi = lo + CHUNK; if (hi > N_NODES) hi = N_NODES;

    int s = 0;
    for (int i = lo; i < hi; i++) s += deg[i];
    sums[t] = s;
    __syncthreads();
    // Hillis-Steele inclusive scan
    for (int d = 1; d < 1024; d <<= 1) {
        int v = (t >= d) ? sums[t - d] : 0;
        __syncthreads();
        sums[t] += v;
        __syncthreads();
    }
    int run = (t == 0) ? 0 : sums[t - 1];
    for (int i = lo; i < hi; i++) {
        off[i] = run;
        cursor[i] = run;
        int dg = deg[i];
        dis[i] = rsqrtf((float)(dg + 1));
        run += dg;
    }
    if (t == 1023) off[N_NODES] = run;
}

__global__ void k_fill(const int* __restrict__ row, const int* __restrict__ col,
                       const float* __restrict__ dis, int* cursor,
                       int* __restrict__ crow, float* __restrict__ cnrm)
{
    int e = blockIdx.x * blockDim.x + threadIdx.x;
    if (e >= N_EDGES) return;
    int r = row[e], c = col[e];
    int p = atomicAdd(&cursor[c], 1);
    crow[p] = r;
    cnrm[p] = dis[r] * dis[c];
}

// ---------------------------------------------------------------- tf32 GEMM
__device__ __forceinline__ uint32_t f2tf(float x) {
    uint32_t u;
    asm("cvt.rna.tf32.f32 %0, %1;" : "=r"(u) : "f"(x));
    return u;
}

#define MMA_TF32(d, a, b)                                                     \
    asm volatile(                                                             \
        "mma.sync.aligned.m16n8k8.row.col.f32.tf32.tf32.f32 "                 \
        "{%0,%1,%2,%3},{%4,%5,%6,%7},{%8,%9},{%0,%1,%2,%3};"                  \
        : "+f"((d)[0]), "+f"((d)[1]), "+f"((d)[2]), "+f"((d)[3])              \
        : "r"((a)[0]), "r"((a)[1]), "r"((a)[2]), "r"((a)[3]),                 \
          "r"((b)[0]), "r"((b)[1]))

// C[M,BN] = op(A)[M,K] @ B[K,BN].  op = relu(A + bias[k]) if FUSE.
// WM x WN per-warp tile via m16n8k8 tf32.
template<int BM, int BN, int BK, int WARPS, int WARPS_M, int WM, int WN, bool FUSE>
__global__ void __launch_bounds__(WARPS * 32)
k_gemm_tc(const float* __restrict__ A, const float* __restrict__ B,
          float* __restrict__ C, const float* __restrict__ bias, int M, int K)
{
    constexpr int MT = WM / 16, NT = WN / 8;
    constexpr int SA = BK + 4;   // A smem row stride (conflict-free frag loads)
    constexpr int SB = BN + 8;   // B smem row stride (conflict-free frag loads)
    __shared__ uint32_t As[BM * SA];
    __shared__ uint32_t Bs[BK * SB];

    const int tid = threadIdx.x, wid = tid >> 5, lane = tid & 31;
    const int wm = wid % WARPS_M, wn = wid / WARPS_M;
    const int g = lane >> 2, tig = lane & 3;
    const int m0 = blockIdx.x * BM;

    float acc[MT][NT][4];
#pragma unroll
    for (int i = 0; i < MT; i++)
#pragma unroll
        for (int j = 0; j < NT; j++)
#pragma unroll
            for (int q = 0; q < 4; q++) acc[i][j][q] = 0.f;

    for (int k0 = 0; k0 < K; k0 += BK) {
        // --- A tile: As[m][k] (tf32) ---
#pragma unroll
        for (int i = tid; i < BM * BK / 4; i += WARPS * 32) {
            int r = i / (BK / 4), c4 = i % (BK / 4);
            float4 v = make_float4(0.f, 0.f, 0.f, 0.f);
            if (m0 + r < M) {
                v = *(const float4*)(A + (size_t)(m0 + r) * K + k0 + c4 * 4);
                if (FUSE) {
                    float4 bb = *(const float4*)(bias + k0 + c4 * 4);
                    v.x = fmaxf(v.x + bb.x, 0.f);
                    v.y = fmaxf(v.y + bb.y, 0.f);
                    v.z = fmaxf(v.z + bb.z, 0.f);
                    v.w = fmaxf(v.w + bb.w, 0.f);
                }
            }
            uint32_t* p = &As[r * SA + c4 * 4];
            p[0] = f2tf(v.x); p[1] = f2tf(v.y); p[2] = f2tf(v.z); p[3] = f2tf(v.w);
        }
        // --- B tile: Bs[k][n] (tf32) ---
#pragma unroll
        for (int i = tid; i < BK * BN / 4; i += WARPS * 32) {
            int kk = i / (BN / 4), c4 = i % (BN / 4);
            float4 v = *(const float4*)(B + (size_t)(k0 + kk) * BN + c4 * 4);
            uint32_t* p = &Bs[kk * SB + c4 * 4];
            p[0] = f2tf(v.x); p[1] = f2tf(v.y); p[2] = f2tf(v.z); p[3] = f2tf(v.w);
        }
        __syncthreads();

#pragma unroll
        for (int kk = 0; kk < BK / 8; kk++) {
            uint32_t af[MT][4], bf[NT][2];
#pragma unroll
            for (int mt = 0; mt < MT; mt++) {
                int r = wm * WM + mt * 16;
                af[mt][0] = As[(r + g)     * SA + kk * 8 + tig];
                af[mt][1] = As[(r + g + 8) * SA + kk * 8 + tig];
                af[mt][2] = As[(r + g)     * SA + kk * 8 + tig + 4];
                af[mt][3] = As[(r + g + 8) * SA + kk * 8 + tig + 4];
            }
#pragma unroll
            for (int nt = 0; nt < NT; nt++) {
                int c = wn * WN + nt * 8;
                bf[nt][0] = Bs[(kk * 8 + tig)     * SB + c + g];
                bf[nt][1] = Bs[(kk * 8 + tig + 4) * SB + c + g];
            }
#pragma unroll
            for (int mt = 0; mt < MT; mt++)
#pragma unroll
                for (int nt = 0; nt < NT; nt++)
                    MMA_TF32(acc[mt][nt], af[mt], bf[nt]);
        }
        __syncthreads();
    }

    // --- epilogue ---
#pragma unroll
    for (int mt = 0; mt < MT; mt++) {
        int r0 = m0 + wm * WM + mt * 16 + g;
#pragma unroll
        for (int nt = 0; nt < NT; nt++) {
            int c = wn * WN + nt * 8 + 2 * tig;
            if (r0 < M)
                *(float2*)(C + (size_t)r0 * BN + c) =
                    make_float2(acc[mt][nt][0], acc[mt][nt][1]);
            if (r0 + 8 < M)
                *(float2*)(C + (size_t)(r0 + 8) * BN + c) =
                    make_float2(acc[mt][nt][2], acc[mt][nt][3]);
        }
    }
}

// ---------------------------------------------------------------- CSR gather
// One warp per (node, 32-feature chunk). acc init = self loop (dis^2 * h[c]).
template<int F>
__global__ void k_gather(const float* __restrict__ h, float* __restrict__ agg,
                         const int* __restrict__ off, const int* __restrict__ crow,
                         const float* __restrict__ cnrm, const float* __restrict__ dis)
{
    constexpr int CH = F / 32;
    int gw = (blockIdx.x * blockDim.x + threadIdx.x) >> 5;
    int lane = threadIdx.x & 31;
    int node = gw / CH, ch = gw % CH;
    if (node >= N_NODES) return;
    int f = ch * 32 + lane;

    float d = dis[node];
    float acc = h[(size_t)node * F + f] * d * d;

    int s = off[node], e = off[node + 1];
    int j = s;
    for (; j + 1 < e; j += 2) {
        int   r0 = __ldg(&crow[j]),     r1 = __ldg(&crow[j + 1]);
        float n0 = __ldg(&cnrm[j]),     n1 = __ldg(&cnrm[j + 1]);
        float v0 = h[(size_t)r0 * F + f];
        float v1 = h[(size_t)r1 * F + f];
        acc = fmaf(v0, n0, acc);
        acc = fmaf(v1, n1, acc);
    }
    if (j < e)
        acc = fmaf(h[(size_t)__ldg(&crow[j]) * F + f], __ldg(&cnrm[j]), acc);

    agg[(size_t)node * F + f] = acc;
}

// ---------------------------------------------------------------- max pool
__global__ void k_zero_pool(float* pool) {
    int i = blockIdx.x * blockDim.x + threadIdx.x;
    if (i < N_GRAPHS * H2) pool[i] = 0.f;
}

// batch is sorted; relu output >= 0 so uint atomicMax on float bits is valid.
#define POOL_CHUNK 512
__global__ void k_pool(const float* __restrict__ agg2, const float* __restrict__ b2,
                       const int* __restrict__ batch, float* __restrict__ pool)
{
    int f = threadIdx.x;                 // 64 threads = 64 features
    int start = blockIdx.x * POOL_CHUNK;
    int end = start + POOL_CHUNK;
    if (end > N_NODES) end = N_NODES;
    float bb = b2[f];
    int gcur = -1;
    float m = 0.f;
    for (int i = start; i < end; i++) {
        int g = batch[i];
        if (g != gcur) {
            if (gcur >= 0)
                atomicMax((unsigned int*)&pool[gcur * H2 + f], __float_as_uint(m));
            gcur = g;
            m = 0.f;
        }
        float v = agg2[(size_t)i * H2 + f] + bb;
        v = v > 0.f ? v : 0.f;
        m = fmaxf(m, v);
    }
    if (gcur >= 0)
        atomicMax((unsigned int*)&pool[gcur * H2 + f], __float_as_uint(m));
}

// ---------------------------------------------------------------- final FC
__global__ void k_fc(const float* __restrict__ pool, const float* __restrict__ Wfc,
                     const float* __restrict__ bfc, float* __restrict__ out)
{
    __shared__ float w[H2 * OUT_DIM];
    __shared__ float bb[OUT_DIM];
    int tid = threadIdx.x;
    for (int i = tid; i < H2 * OUT_DIM; i += blockDim.x) w[i] = Wfc[i];
    if (tid < OUT_DIM) bb[tid] = bfc[tid];
    __syncthreads();
    if (tid < N_GRAPHS) {
        float acc[OUT_DIM];
#pragma unroll
        for (int j = 0; j < OUT_DIM; j++) acc[j] = bb[j];
        for (int k = 0; k < H2; k++) {
            float g = pool[tid * H2 + k];
#pragma unroll
            for (int j = 0; j < OUT_DIM; j++) acc[j] = fmaf(g, w[k * OUT_DIM + j], acc[j]);
        }
#pragma unroll
        for (int j = 0; j < OUT_DIM; j++) out[tid * OUT_DIM + j] = acc[j];
    }
}

// ---------------------------------------------------------------- launch
extern "C" void kernel_launch(void* const* d_in, const int* in_sizes, int n_in,
                              void* d_out, int out_size)
{
    const float* x    = (const float*)d_in[0];
    const int*   ei   = (const int*)d_in[1];
    const int*   batch= (const int*)d_in[2];
    const float* W1   = (const float*)d_in[3];
    const float* b1   = (const float*)d_in[4];
    const float* W2   = (const float*)d_in[5];
    const float* b2   = (const float*)d_in[6];
    const float* Wfc  = (const float*)d_in[7];
    const float* bfc  = (const float*)d_in[8];
    float* out = (float*)d_out;

    const int* row = ei;
    const int* col = ei + N_EDGES;

    int *deg, *off, *cursor, *crow;
    float *dis, *cnrm, *h1, *agg1, *h2, *agg2, *pool;
    cudaGetSymbolAddress((void**)&deg,    g_deg);
    cudaGetSymbolAddress((void**)&off,    g_off);
    cudaGetSymbolAddress((void**)&cursor, g_cursor);
    cudaGetSymbolAddress((void**)&dis,    g_dis);
    cudaGetSymbolAddress((void**)&crow,   g_crow);
    cudaGetSymbolAddress((void**)&cnrm,   g_cnrm);
    cudaGetSymbolAddress((void**)&h1,     g_h1);
    cudaGetSymbolAddress((void**)&agg1,   g_agg1);
    cudaGetSymbolAddress((void**)&h2,     g_h2);
    cudaGetSymbolAddress((void**)&agg2,   g_agg2);
    cudaGetSymbolAddress((void**)&pool,   g_pool);

    // CSR build
    k_zero_deg<<<(N_NODES + 255) / 256, 256>>>(deg);
    k_count<<<(N_EDGES + 255) / 256, 256>>>(col, deg);
    k_scan<<<1, 1024>>>(deg, off, cursor, dis);
    k_fill<<<(N_EDGES + 255) / 256, 256>>>(row, col, dis, cursor, crow, cnrm);

    // layer 1: h1 = x @ W1 ; agg1 = gather(h1)
    k_gemm_tc<128, 128, 32, 8, 4, 32, 64, false>
        <<<(N_NODES + 127) / 128, 256>>>(x, W1, h1, nullptr, N_NODES, IN_DIM);
    {
        int warps = N_NODES * (H1 / 32);
        k_gather<H1><<<(warps * 32 + 255) / 256, 256>>>(h1, agg1, off, crow, cnrm, dis);
    }

    // layer 2: h2 = relu(agg1 + b1) @ W2 ; agg2 = gather(h2)
    k_gemm_tc<128, 64, 32, 8, 8, 16, 64, true>
        <<<(N_NODES + 127) / 128, 256>>>(agg1, W2, h2, b1, N_NODES, H1);
    {
        int warps = N_NODES * (H2 / 32);
        k_gather<H2><<<(warps * 32 + 255) / 256, 256>>>(h2, agg2, off, crow, cnrm, dis);
    }

    // pool + fc
    k_zero_pool<<<(N_GRAPHS * H2 + 255) / 256, 256>>>(pool);
    k_pool<<<(N_NODES + POOL_CHUNK - 1) / POOL_CHUNK, H2>>>(agg2, b2, batch, pool);
    k_fc<<<1, 128>>>(pool, Wfc, bfc, out);
}

// round 3
// speedup vs baseline: 1.4633x; 1.3745x over previous
#include <cuda_runtime.h>
#include <cuda_bf16.h>
#include <cstdint>

// ----------------------------------------------------------------------------
// GCN: agg1 = relu(Ahat (x@W1) + b1); agg2 = relu(Ahat (agg1@W2) + b2);
//      out = segment_max(agg2, batch) @ Wfc + bfc
// CSR build overlapped with GEMM1 (2nd stream). GEMMs: tf32 mma + cp.async
// double buffering. Gathers: warp/node, vectorized, bias+relu fused.
// ----------------------------------------------------------------------------

#define N_NODES 50000
#define N_EDGES 800000
#define N_GRAPHS 128
#define IN_DIM 256
#define H1 128
#define H2 64
#define OUT_DIM 10

__device__ int   g_deg[N_NODES];
__device__ int   g_off[N_NODES + 1];
__device__ int   g_cursor[N_NODES];
__device__ float g_dis[N_NODES];
__device__ int2  g_cedge[N_EDGES];          // (row, norm-bits) packed
__device__ float g_h1[(size_t)N_NODES * H1];
__device__ float g_agg1[(size_t)N_NODES * H1];
__device__ float g_h2[(size_t)N_NODES * H2];
__device__ float g_agg2[(size_t)N_NODES * H2];
__device__ float g_pool[N_GRAPHS * H2];

// ---------------------------------------------------------------- CSR build
__global__ void k_zero_deg(int* deg) {
    int i = blockIdx.x * blockDim.x + threadIdx.x;
    if (i < N_NODES) deg[i] = 0;
}

__global__ void k_count(const int* __restrict__ col, int* deg) {
    int e = blockIdx.x * blockDim.x + threadIdx.x;
    if (e < N_EDGES) atomicAdd(&deg[col[e]], 1);
}

__global__ void __launch_bounds__(1024)
k_scan(const int* __restrict__ deg, int* __restrict__ off,
       int* __restrict__ cursor, float* __restrict__ dis)
{
    __shared__ int sums[1024];
    const int t = threadIdx.x;
    const int CHUNK = (N_NODES + 1023) / 1024;
    int lo = t * CHUNK; if (lo > N_NODES) lo = N_NODES;
    int hi = lo + CHUNK; if (hi > N_NODES) hi = N_NODES;

    int s = 0;
    for (int i = lo; i < hi; i++) s += deg[i];
    sums[t] = s;
    __syncthreads();
    for (int d = 1; d < 1024; d <<= 1) {
        int v = (t >= d) ? sums[t - d] : 0;
        __syncthreads();
        sums[t] += v;
        __syncthreads();
    }
    int run = (t == 0) ? 0 : sums[t - 1];
    for (int i = lo; i < hi; i++) {
        off[i] = run;
        cursor[i] = run;
        int dg = deg[i];
        dis[i] = rsqrtf((float)(dg + 1));
        run += dg;
    }
    if (t == 1023) off[N_NODES] = run;
}

__global__ void k_fill(const int* __restrict__ row, const int* __restrict__ col,
                       const float* __restrict__ dis, int* cursor,
                       int2* __restrict__ cedge)
{
    int e = blockIdx.x * blockDim.x + threadIdx.x;
    if (e >= N_EDGES) return;
    int r = row[e], c = col[e];
    int p = atomicAdd(&cursor[c], 1);
    cedge[p] = make_int2(r, __float_as_int(dis[r] * dis[c]));
}

// ---------------------------------------------------------------- tf32 GEMM (cp.async, double-buffered)
#define MMA_TF32(d, a, b)                                                     \
    asm volatile(                                                             \
        "mma.sync.aligned.m16n8k8.row.col.f32.tf32.tf32.f32 "                 \
        "{%0,%1,%2,%3},{%4,%5,%6,%7},{%8,%9},{%0,%1,%2,%3};"                  \
        : "+f"((d)[0]), "+f"((d)[1]), "+f"((d)[2]), "+f"((d)[3])              \
        : "r"((a)[0]), "r"((a)[1]), "r"((a)[2]), "r"((a)[3]),                 \
          "r"((b)[0]), "r"((b)[1]))

__device__ __forceinline__ void cp16(uint32_t saddr, const void* gaddr, int sz) {
    asm volatile("cp.async.cg.shared.global [%0], [%1], 16, %2;"
                 :: "r"(saddr), "l"(gaddr), "r"(sz));
}

template<int BM, int BN, int BK, int WARPS, int WARPS_M, int WM, int WN>
__global__ void __launch_bounds__(WARPS * 32)
k_gemm_ca(const float* __restrict__ A, const float* __restrict__ B,
          float* __restrict__ C, int M, int K)
{
    constexpr int MT = WM / 16, NT = WN / 8;
    constexpr int SA = BK + 4;
    constexpr int SB = BN + 8;
    __shared__ float As[2][BM * SA];
    __shared__ float Bs[2][BK * SB];

    const int tid = threadIdx.x, wid = tid >> 5, lane = tid & 31;
    const int wm = wid % WARPS_M, wn = wid / WARPS_M;
    const int g = lane >> 2, tig = lane & 3;
    const int m0 = blockIdx.x * BM;

    float acc[MT][NT][4];
#pragma unroll
    for (int i = 0; i < MT; i++)
#pragma unroll
        for (int j = 0; j < NT; j++)
#pragma unroll
            for (int q = 0; q < 4; q++) acc[i][j][q] = 0.f;

    auto loadTiles = [&](int buf, int k0) {
#pragma unroll
        for (int i = tid; i < BM * BK / 4; i += WARPS * 32) {
            int r = i / (BK / 4), c4 = i % (BK / 4);
            cp16((uint32_t)__cvta_generic_to_shared(&As[buf][r * SA + c4 * 4]),
                 A + (size_t)(m0 + r) * K + k0 + c4 * 4,
                 (m0 + r < M) ? 16 : 0);
        }
#pragma unroll
        for (int i = tid; i < BK * BN / 4; i += WARPS * 32) {
            int kk = i / (BN / 4), c4 = i % (BN / 4);
            cp16((uint32_t)__cvta_generic_to_shared(&Bs[buf][kk * SB + c4 * 4]),
                 B + (size_t)(k0 + kk) * BN + c4 * 4, 16);
        }
        asm volatile("cp.async.commit_group;");
    };

    const int nk = K / BK;
    loadTiles(0, 0);
    for (int t = 0; t < nk; t++) {
        if (t + 1 < nk) {
            loadTiles((t + 1) & 1, (t + 1) * BK);
            asm volatile("cp.async.wait_group 1;");
        } else {
            asm volatile("cp.async.wait_group 0;");
        }
        __syncthreads();
        const int buf = t & 1;

#pragma unroll
        for (int kk = 0; kk < BK / 8; kk++) {
            uint32_t af[MT][4], bf[NT][2];
#pragma unroll
            for (int mt = 0; mt < MT; mt++) {
                int r = wm * WM + mt * 16;
                af[mt][0] = __float_as_uint(As[buf][(r + g)     * SA + kk * 8 + tig]);
                af[mt][1] = __float_as_uint(As[buf][(r + g + 8) * SA + kk * 8 + tig]);
                af[mt][2] = __float_as_uint(As[buf][(r + g)     * SA + kk * 8 + tig + 4]);
                af[mt][3] = __float_as_uint(As[buf][(r + g + 8) * SA + kk * 8 + tig + 4]);
            }
#pragma unroll
            for (int nt = 0; nt < NT; nt++) {
                int c = wn * WN + nt * 8;
                bf[nt][0] = __float_as_uint(Bs[buf][(kk * 8 + tig)     * SB + c + g]);
                bf[nt][1] = __float_as_uint(Bs[buf][(kk * 8 + tig + 4) * SB + c + g]);
            }
#pragma unroll
            for (int mt = 0; mt < MT; mt++)
#pragma unroll
                for (int nt = 0; nt < NT; nt++)
                    MMA_TF32(acc[mt][nt], af[mt], bf[nt]);
        }
        __syncthreads();
    }

#pragma unroll
    for (int mt = 0; mt < MT; mt++) {
        int r0 = m0 + wm * WM + mt * 16 + g;
#pragma unroll
        for (int nt = 0; nt < NT; nt++) {
            int c = wn * WN + nt * 8 + 2 * tig;
            if (r0 < M)
                *(float2*)(C + (size_t)r0 * BN + c) =
                    make_float2(acc[mt][nt][0], acc[mt][nt][1]);
            if (r0 + 8 < M)
                *(float2*)(C + (size_t)(r0 + 8) * BN + c) =
                    make_float2(acc[mt][nt][2], acc[mt][nt][3]);
        }
    }
}

// ---------------------------------------------------------------- gathers (warp per node)
// agg[node] = relu( dis^2*h[node] + sum_e nrm_e * h[row_e] + bias )
__global__ void k_gather128(const float* __restrict__ h, float* __restrict__ agg,
                            const int* __restrict__ off, const int2* __restrict__ ce,
                            const float* __restrict__ dis, const float* __restrict__ bias)
{
    int node = (blockIdx.x * blockDim.x + threadIdx.x) >> 5;
    int lane = threadIdx.x & 31;
    if (node >= N_NODES) return;

    float d = dis[node];
    float dd = d * d;
    float4 acc = *(const float4*)(h + (size_t)node * 128 + lane * 4);
    acc.x *= dd; acc.y *= dd; acc.z *= dd; acc.w *= dd;

    int s = off[node], e = off[node + 1];
    int j = s;
    for (; j + 1 < e; j += 2) {
        int2 p0 = __ldg(&ce[j]);
        int2 p1 = __ldg(&ce[j + 1]);
        float n0 = __int_as_float(p0.y), n1 = __int_as_float(p1.y);
        float4 v0 = *(const float4*)(h + (size_t)p0.x * 128 + lane * 4);
        float4 v1 = *(const float4*)(h + (size_t)p1.x * 128 + lane * 4);
        acc.x = fmaf(v0.x, n0, acc.x); acc.y = fmaf(v0.y, n0, acc.y);
        acc.z = fmaf(v0.z, n0, acc.z); acc.w = fmaf(v0.w, n0, acc.w);
        acc.x = fmaf(v1.x, n1, acc.x); acc.y = fmaf(v1.y, n1, acc.y);
        acc.z = fmaf(v1.z, n1, acc.z); acc.w = fmaf(v1.w, n1, acc.w);
    }
    if (j < e) {
        int2 p = __ldg(&ce[j]);
        float n = __int_as_float(p.y);
        float4 v = *(const float4*)(h + (size_t)p.x * 128 + lane * 4);
        acc.x = fmaf(v.x, n, acc.x); acc.y = fmaf(v.y, n, acc.y);
        acc.z = fmaf(v.z, n, acc.z); acc.w = fmaf(v.w, n, acc.w);
    }
    float4 bb = *(const float4*)(bias + lane * 4);
    acc.x = fmaxf(acc.x + bb.x, 0.f); acc.y = fmaxf(acc.y + bb.y, 0.f);
    acc.z = fmaxf(acc.z + bb.z, 0.f); acc.w = fmaxf(acc.w + bb.w, 0.f);
    *(float4*)(agg + (size_t)node * 128 + lane * 4) = acc;
}

__global__ void k_gather64(const float* __restrict__ h, float* __restrict__ agg,
                           const int* __restrict__ off, const int2* __restrict__ ce,
                           const float* __restrict__ dis, const float* __restrict__ bias)
{
    int node = (blockIdx.x * blockDim.x + threadIdx.x) >> 5;
    int lane = threadIdx.x & 31;
    if (node >= N_NODES) return;

    float d = dis[node];
    float dd = d * d;
    float2 acc = *(const float2*)(h + (size_t)node * 64 + lane * 2);
    acc.x *= dd; acc.y *= dd;

    int s = off[node], e = off[node + 1];
    int j = s;
    for (; j + 1 < e; j += 2) {
        int2 p0 = __ldg(&ce[j]);
        int2 p1 = __ldg(&ce[j + 1]);
        float n0 = __int_as_float(p0.y), n1 = __int_as_float(p1.y);
        float2 v0 = *(const float2*)(h + (size_t)p0.x * 64 + lane * 2);
        float2 v1 = *(const float2*)(h + (size_t)p1.x * 64 + lane * 2);
        acc.x = fmaf(v0.x, n0, acc.x); acc.y = fmaf(v0.y, n0, acc.y);
        acc.x = fmaf(v1.x, n1, acc.x); acc.y = fmaf(v1.y, n1, acc.y);
    }
    if (j < e) {
        int2 p = __ldg(&ce[j]);
        float n = __int_as_float(p.y);
        float2 v = *(const float2*)(h + (size_t)p.x * 64 + lane * 2);
        acc.x = fmaf(v.x, n, acc.x); acc.y = fmaf(v.y, n, acc.y);
    }
    float2 bb = *(const float2*)(bias + lane * 2);
    acc.x = fmaxf(acc.x + bb.x, 0.f);
    acc.y = fmaxf(acc.y + bb.y, 0.f);
    *(float2*)(agg + (size_t)node * 64 + lane * 2) = acc;
}

// ---------------------------------------------------------------- max pool
__global__ void k_zero_pool(float* pool) {
    int i = blockIdx.x * blockDim.x + threadIdx.x;
    if (i < N_GRAPHS * H2) pool[i] = 0.f;
}

#define POOL_CHUNK 128
__global__ void k_pool(const float* __restrict__ agg2,
                       const int* __restrict__ batch, float* __restrict__ pool)
{
    int f = threadIdx.x;                 // 64 threads = 64 features
    int start = blockIdx.x * POOL_CHUNK;
    int end = start + POOL_CHUNK;
    if (end > N_NODES) end = N_NODES;
    int gcur = -1;
    float m = 0.f;
    for (int i = start; i < end; i++) {
        int g = batch[i];
        if (g != gcur) {
            if (gcur >= 0)
                atomicMax((unsigned int*)&pool[gcur * H2 + f], __float_as_uint(m));
            gcur = g;
            m = 0.f;
        }
        m = fmaxf(m, agg2[(size_t)i * H2 + f]);
    }
    if (gcur >= 0)
        atomicMax((unsigned int*)&pool[gcur * H2 + f], __float_as_uint(m));
}

// ---------------------------------------------------------------- final FC
__global__ void k_fc(const float* __restrict__ pool, const float* __restrict__ Wfc,
                     const float* __restrict__ bfc, float* __restrict__ out)
{
    __shared__ float w[H2 * OUT_DIM];
    __shared__ float bb[OUT_DIM];
    int tid = threadIdx.x;
    for (int i = tid; i < H2 * OUT_DIM; i += blockDim.x) w[i] = Wfc[i];
    if (tid < OUT_DIM) bb[tid] = bfc[tid];
    __syncthreads();
    if (tid < N_GRAPHS) {
        float acc[OUT_DIM];
#pragma unroll
        for (int j = 0; j < OUT_DIM; j++) acc[j] = bb[j];
        for (int k = 0; k < H2; k++) {
            float g = pool[tid * H2 + k];
#pragma unroll
            for (int j = 0; j < OUT_DIM; j++) acc[j] = fmaf(g, w[k * OUT_DIM + j], acc[j]);
        }
#pragma unroll
        for (int j = 0; j < OUT_DIM; j++) out[tid * OUT_DIM + j] = acc[j];
    }
}

// ---------------------------------------------------------------- launch
extern "C" void kernel_launch(void* const* d_in, const int* in_sizes, int n_in,
                              void* d_out, int out_size)
{
    const float* x    = (const float*)d_in[0];
    const int*   ei   = (const int*)d_in[1];
    const int*   batch= (const int*)d_in[2];
    const float* W1   = (const float*)d_in[3];
    const float* b1   = (const float*)d_in[4];
    const float* W2   = (const float*)d_in[5];
    const float* b2   = (const float*)d_in[6];
    const float* Wfc  = (const float*)d_in[7];
    const float* bfc  = (const float*)d_in[8];
    float* out = (float*)d_out;

    const int* row = ei;
    const int* col = ei + N_EDGES;

    int *deg, *off, *cursor;
    int2* cedge;
    float *dis, *h1, *agg1, *h2, *agg2, *pool;
    cudaGetSymbolAddress((void**)&deg,    g_deg);
    cudaGetSymbolAddress((void**)&off,    g_off);
    cudaGetSymbolAddress((void**)&cursor, g_cursor);
    cudaGetSymbolAddress((void**)&dis,    g_dis);
    cudaGetSymbolAddress((void**)&cedge,  g_cedge);
    cudaGetSymbolAddress((void**)&h1,     g_h1);
    cudaGetSymbolAddress((void**)&agg1,   g_agg1);
    cudaGetSymbolAddress((void**)&h2,     g_h2);
    cudaGetSymbolAddress((void**)&agg2,   g_agg2);
    cudaGetSymbolAddress((void**)&pool,   g_pool);

    // side stream + fork/join events (created fresh each call; kernel_launch
    // only runs twice — correctness + capture — so no unbounded leak)
    cudaStream_t s2;
    cudaStreamCreateWithFlags(&s2, cudaStreamNonBlocking);
    cudaEvent_t evF, evJ;
    cudaEventCreateWithFlags(&evF, cudaEventDisableTiming);
    cudaEventCreateWithFlags(&evJ, cudaEventDisableTiming);

    // fork: CSR build on s2, GEMM1 on main stream
    cudaEventRecord(evF, 0);
    cudaStreamWaitEvent(s2, evF, 0);
    k_zero_deg<<<(N_NODES + 255) / 256, 256, 0, s2>>>(deg);
    k_count<<<(N_EDGES + 255) / 256, 256, 0, s2>>>(col, deg);
    k_scan<<<1, 1024, 0, s2>>>(deg, off, cursor, dis);
    k_fill<<<(N_EDGES + 255) / 256, 256, 0, s2>>>(row, col, dis, cursor, cedge);
    cudaEventRecord(evJ, s2);

    // GEMM1: h1 = x @ W1   (BM=128,BN=128,BK=16, 8 warps, 4x2 of 32x64)
    k_gemm_ca<128, 128, 16, 8, 4, 32, 64>
        <<<(N_NODES + 127) / 128, 256>>>(x, W1, h1, N_NODES, IN_DIM);

    // join, then gather1 (needs CSR + h1)
    cudaStreamWaitEvent(0, evJ, 0);
    k_gather128<<<(N_NODES * 32 + 255) / 256, 256>>>(h1, agg1, off, cedge, dis, b1);

    // GEMM2: h2 = agg1 @ W2   (BM=128,BN=64,BK=16, 8 warps, 4x2 of 32x32)
    k_gemm_ca<128, 64, 16, 8, 4, 32, 32>
        <<<(N_NODES + 127) / 128, 256>>>(agg1, W2, h2, N_NODES, H1);
    k_gather64<<<(N_NODES * 32 + 255) / 256, 256>>>(h2, agg2, off, cedge, dis, b2);

    // pool + fc
    k_zero_pool<<<(N_GRAPHS * H2 + 255) / 256, 256>>>(pool);
    k_pool<<<(N_NODES + POOL_CHUNK - 1) / POOL_CHUNK, H2>>>(agg2, batch, pool);
    k_fc<<<1, 128>>>(pool, Wfc, bfc, out);
}